// round 1
// baseline (speedup 1.0000x reference)
#include <cuda_runtime.h>

#define N_NODES 20000
#define N_EDGES 640000
#define D 128

// ---- scratch (no allocations allowed) ----
__device__ int   g_deg[N_NODES];
__device__ int   g_cursor[N_NODES];
__device__ int   g_rowstart[N_NODES + 1];
__device__ int   g_csr[N_EDGES];
__device__ float g_x[N_NODES * D];   // (1+eps)*h + agg  (GEMM input)
__device__ float g_h[N_NODES * D];   // current node features between layers

// ---------------------------------------------------------------------------
__global__ void zero_counts_kernel() {
    int i = blockIdx.x * blockDim.x + threadIdx.x;
    if (i < N_NODES) { g_deg[i] = 0; g_cursor[i] = 0; }
}

__global__ void count_deg_kernel(const int* __restrict__ ei) {
    int e = blockIdx.x * blockDim.x + threadIdx.x;
    if (e < N_EDGES) atomicAdd(&g_deg[ei[N_EDGES + e]], 1);
}

// single-block exclusive scan of g_deg -> g_rowstart (20000 elements)
__global__ void scan_deg_kernel() {
    __shared__ int partial[1024];
    const int tid = threadIdx.x;
    const int CH  = (N_NODES + 1023) / 1024;   // 20
    const int base = tid * CH;

    int s = 0;
    for (int j = 0; j < CH; j++) {
        int idx = base + j;
        if (idx < N_NODES) s += g_deg[idx];
    }
    partial[tid] = s;
    __syncthreads();

    // Hillis-Steele inclusive scan over the 1024 partials
    for (int off = 1; off < 1024; off <<= 1) {
        int v = 0;
        if (tid >= off) v = partial[tid - off];
        __syncthreads();
        if (tid >= off) partial[tid] += v;
        __syncthreads();
    }

    int run = (tid > 0) ? partial[tid - 1] : 0;   // exclusive prefix for this chunk
    for (int j = 0; j < CH; j++) {
        int idx = base + j;
        if (idx < N_NODES) {
            g_rowstart[idx] = run;
            run += g_deg[idx];
        }
    }
    if (tid == 1023) g_rowstart[N_NODES] = partial[1023];  // total edges
}

__global__ void fill_csr_kernel(const int* __restrict__ ei) {
    int e = blockIdx.x * blockDim.x + threadIdx.x;
    if (e < N_EDGES) {
        int s = ei[e];
        int d = ei[N_EDGES + e];
        int pos = atomicAdd(&g_cursor[d], 1);
        g_csr[g_rowstart[d] + pos] = s;
    }
}

// ---------------------------------------------------------------------------
// x[i,:] = hin[i,:] + sum_{j in nbrs(i)} hin[j,:]
// one block (128 threads) per node; thread d owns column d.
__global__ void aggregate_kernel(const float* __restrict__ hin) {
    const int i = blockIdx.x;
    const int d = threadIdx.x;
    const int beg = g_rowstart[i];
    const int end = g_rowstart[i + 1];

    float acc = __ldg(&hin[(long)i * D + d]);
    int k = beg;
    // unroll-by-4 with prefetched indices to expose MLP to L2
    for (; k + 4 <= end; k += 4) {
        int j0 = g_csr[k + 0];
        int j1 = g_csr[k + 1];
        int j2 = g_csr[k + 2];
        int j3 = g_csr[k + 3];
        float v0 = __ldg(&hin[(long)j0 * D + d]);
        float v1 = __ldg(&hin[(long)j1 * D + d]);
        float v2 = __ldg(&hin[(long)j2 * D + d]);
        float v3 = __ldg(&hin[(long)j3 * D + d]);
        acc += v0 + v1 + v2 + v3;
    }
    for (; k < end; k++) {
        int j = g_csr[k];
        acc += __ldg(&hin[(long)j * D + d]);
    }
    g_x[(long)i * D + d] = acc;
}

// ---------------------------------------------------------------------------
// Y[0:nrows, 0:128] = g_x @ W + b
// block: 256 threads, 64 rows x 128 cols. per-thread 8 rows x 4 cols.
__global__ __launch_bounds__(256) void gemm128_kernel(
    const float* __restrict__ W,
    const float* __restrict__ bias,
    float* __restrict__ Y,
    int nrows)
{
    __shared__ float Ws[64][128];   // 32 KB : W[k0+k][c]
    __shared__ float Xs[64][64];    // 16 KB : X[row0+r][k0+k]

    const int tid  = threadIdx.x;
    const int row0 = blockIdx.x * 64;
    const int cg   = (tid & 31) * 4;   // col base 0..124
    const int rg   = (tid >> 5) * 8;   // row base 0..56

    float acc[8][4];
#pragma unroll
    for (int r = 0; r < 8; r++)
#pragma unroll
        for (int c = 0; c < 4; c++) acc[r][c] = 0.f;

#pragma unroll
    for (int k0 = 0; k0 < 128; k0 += 64) {
        // load W tile: 64 x 128
        for (int idx = tid; idx < 64 * 128; idx += 256) {
            int k = idx >> 7, c = idx & 127;
            Ws[k][c] = __ldg(&W[(k0 + k) * 128 + c]);
        }
        // load X tile: 64 x 64
        for (int idx = tid; idx < 64 * 64; idx += 256) {
            int r = idx >> 6, k = idx & 63;
            int row = row0 + r;
            Xs[r][k] = (row < nrows) ? g_x[(long)row * D + k0 + k] : 0.f;
        }
        __syncthreads();

#pragma unroll 8
        for (int k = 0; k < 64; k++) {
            float4 w = *(const float4*)&Ws[k][cg];
#pragma unroll
            for (int r = 0; r < 8; r++) {
                float xv = Xs[rg + r][k];
                acc[r][0] += xv * w.x;
                acc[r][1] += xv * w.y;
                acc[r][2] += xv * w.z;
                acc[r][3] += xv * w.w;
            }
        }
        __syncthreads();
    }

    float4 bv = *(const float4*)&bias[cg];
#pragma unroll
    for (int r = 0; r < 8; r++) {
        int row = row0 + rg + r;
        if (row < nrows) {
            float4 o;
            o.x = acc[r][0] + bv.x;
            o.y = acc[r][1] + bv.y;
            o.z = acc[r][2] + bv.z;
            o.w = acc[r][3] + bv.w;
            *(float4*)&Y[(long)row * D + cg] = o;
        }
    }
}

// ---------------------------------------------------------------------------
extern "C" void kernel_launch(void* const* d_in, const int* in_sizes, int n_in,
                              void* d_out, int out_size) {
    const float* h  = (const float*)d_in[0];
    const int*   ei = (const int*)d_in[1];
    const float* Wt[4] = { (const float*)d_in[2], (const float*)d_in[4],
                           (const float*)d_in[6], (const float*)d_in[8] };
    const float* bt[4] = { (const float*)d_in[3], (const float*)d_in[5],
                           (const float*)d_in[7], (const float*)d_in[9] };
    float* out = (float*)d_out;

    // build CSR (dst -> list of src)
    zero_counts_kernel<<<(N_NODES + 255) / 256, 256>>>();
    count_deg_kernel<<<(N_EDGES + 255) / 256, 256>>>(ei);
    scan_deg_kernel<<<1, 1024>>>();
    fill_csr_kernel<<<(N_EDGES + 255) / 256, 256>>>(ei);

    const int gemm_blocks = (N_NODES + 63) / 64;   // 313

    // layer 0
    aggregate_kernel<<<N_NODES, 128>>>(h);
    gemm128_kernel<<<gemm_blocks, 256>>>(Wt[0], bt[0], g_h, N_NODES);
    // layer 1
    aggregate_kernel<<<N_NODES, 128>>>(g_h);
    gemm128_kernel<<<gemm_blocks, 256>>>(Wt[1], bt[1], g_h, N_NODES);
    // layer 2
    aggregate_kernel<<<N_NODES, 128>>>(g_h);
    gemm128_kernel<<<gemm_blocks, 256>>>(Wt[2], bt[2], g_h, N_NODES);
    // layer 3 -> output
    aggregate_kernel<<<N_NODES, 128>>>(g_h);
    gemm128_kernel<<<gemm_blocks, 256>>>(Wt[3], bt[3], out, N_NODES);
}

// round 2
// speedup vs baseline: 1.0284x; 1.0284x over previous
#include <cuda_runtime.h>

#define N_NODES 20000
#define N_EDGES 640000
#define D 128

// ---- scratch (no allocations allowed). .bss zero-init on load; kernels
// self-reset g_deg/g_cursor each invocation so replays are deterministic. ----
__device__ int   g_deg[N_NODES];          // zeroed by scan kernel after use
__device__ int   g_cursor[N_NODES];       // zeroed by scan kernel before fill
__device__ int   g_rowstart[N_NODES + 1];
__device__ int   g_csr[N_EDGES];
__device__ float g_x[N_NODES * D];        // h + agg  (GEMM input)
__device__ float g_h[N_NODES * D];        // node features between layers

// ---------------------------------------------------------------------------
// 1) count in-degree (g_deg must be 0 on entry — guaranteed by scan kernel
//    of the previous invocation, or .bss zero on first call)
__global__ void count_deg_kernel(const int* __restrict__ ei) {
    int e = blockIdx.x * blockDim.x + threadIdx.x;
    if (e < N_EDGES) atomicAdd(&g_deg[ei[N_EDGES + e]], 1);
}

// 2) single-block exclusive scan of g_deg -> g_rowstart, then reset
//    g_deg and g_cursor to 0 for the next phase / next invocation.
__global__ void scan_deg_kernel() {
    __shared__ int partial[1024];
    const int tid = threadIdx.x;
    const int CH  = (N_NODES + 1023) / 1024;   // 20
    const int base = tid * CH;

    int s = 0;
    for (int j = 0; j < CH; j++) {
        int idx = base + j;
        if (idx < N_NODES) s += g_deg[idx];
    }
    partial[tid] = s;
    __syncthreads();

    for (int off = 1; off < 1024; off <<= 1) {
        int v = 0;
        if (tid >= off) v = partial[tid - off];
        __syncthreads();
        if (tid >= off) partial[tid] += v;
        __syncthreads();
    }

    int run = (tid > 0) ? partial[tid - 1] : 0;
    for (int j = 0; j < CH; j++) {
        int idx = base + j;
        if (idx < N_NODES) {
            g_rowstart[idx] = run;
            run += g_deg[idx];
            g_deg[idx]    = 0;   // reset for next invocation
            g_cursor[idx] = 0;   // reset for fill phase
        }
    }
    if (tid == 1023) g_rowstart[N_NODES] = partial[1023];
}

// 3) scatter edges into CSR buckets
__global__ void fill_csr_kernel(const int* __restrict__ ei) {
    int e = blockIdx.x * blockDim.x + threadIdx.x;
    if (e < N_EDGES) {
        int s = ei[e];
        int d = ei[N_EDGES + e];
        int pos = atomicAdd(&g_cursor[d], 1);
        g_csr[g_rowstart[d] + pos] = s;
    }
}

// ---------------------------------------------------------------------------
// 4) aggregation: one WARP per node, lane owns 4 columns (float4).
//    8 edge indices fetched per iteration, shfl-broadcast -> 8 independent
//    512B row loads in flight per warp.
__global__ __launch_bounds__(256) void aggregate_kernel(const float* __restrict__ hin) {
    const int lane = threadIdx.x & 31;
    const int node = blockIdx.x * 8 + (threadIdx.x >> 5);
    const int beg = g_rowstart[node];
    const int end = g_rowstart[node + 1];

    const float4* __restrict__ hv = (const float4*)hin;

    float4 a = hv[node * 32 + lane];
    float acc0 = a.x, acc1 = a.y, acc2 = a.z, acc3 = a.w;

    for (int k = beg; k < end; k += 8) {
        int kk = k + (lane & 7);
        int myj = (kk < end) ? g_csr[kk] : -1;
#pragma unroll
        for (int e = 0; e < 8; e++) {
            int j = __shfl_sync(0xffffffffu, myj, e);
            if (j >= 0) {
                float4 v = hv[j * 32 + lane];
                acc0 += v.x; acc1 += v.y; acc2 += v.z; acc3 += v.w;
            }
        }
    }
    float4 o; o.x = acc0; o.y = acc1; o.z = acc2; o.w = acc3;
    ((float4*)g_x)[node * 32 + lane] = o;
}

// ---------------------------------------------------------------------------
// Y[0:nrows, 0:128] = g_x @ W + b
// 128x128 tile per block, 256 threads, per-thread 8x8 accumulators,
// rank-4 inner update, float4 smem traffic on both operands.
__global__ __launch_bounds__(256, 2) void gemm_kernel(
    const float* __restrict__ W,
    const float* __restrict__ bias,
    float* __restrict__ Y,
    int nrows)
{
    __shared__ float Xs[128][36];   // 18 KB, row stride 36 (float4-aligned)
    __shared__ float Ws[32][128];   // 16 KB

    const int tid  = threadIdx.x;
    const int row0 = blockIdx.x * 128;
    const int ty   = tid >> 4;          // 0..15
    const int tx   = tid & 15;          // 0..15
    const int rbase = ty * 8;
    const int cbase = tx * 8;

    float acc[8][8];
#pragma unroll
    for (int r = 0; r < 8; r++)
#pragma unroll
        for (int c = 0; c < 8; c++) acc[r][c] = 0.f;

#pragma unroll
    for (int k0 = 0; k0 < 128; k0 += 32) {
        // load X tile: 128 rows x 32 k (each thread: 4 float4 loads)
        {
            int r  = tid >> 3;            // 0..31
            int kc = (tid & 7) * 4;       // 0..28
#pragma unroll
            for (int rr = 0; rr < 128; rr += 32) {
                int row = row0 + r + rr;
                float4 v = make_float4(0.f, 0.f, 0.f, 0.f);
                if (row < nrows) v = *(const float4*)&g_x[(long)row * D + k0 + kc];
                *(float4*)&Xs[r + rr][kc] = v;
            }
        }
        // load W tile: 32 k x 128 cols (each thread: 4 float4 loads)
#pragma unroll
        for (int i = 0; i < 4; i++) {
            int idx = tid + i * 256;      // one float4 each
            int k   = idx >> 5;
            int c4  = (idx & 31) * 4;
            *(float4*)&Ws[k][c4] = __ldg((const float4*)&W[(k0 + k) * 128 + c4]);
        }
        __syncthreads();

#pragma unroll
        for (int k = 0; k < 32; k += 4) {
            float4 xf[8];
            float4 w0[4], w1[4];
#pragma unroll
            for (int r = 0; r < 8; r++) xf[r] = *(const float4*)&Xs[rbase + r][k];
#pragma unroll
            for (int kk = 0; kk < 4; kk++) {
                w0[kk] = *(const float4*)&Ws[k + kk][cbase];
                w1[kk] = *(const float4*)&Ws[k + kk][cbase + 4];
            }
#pragma unroll
            for (int kk = 0; kk < 4; kk++) {
#pragma unroll
                for (int r = 0; r < 8; r++) {
                    float xv = (kk == 0) ? xf[r].x : (kk == 1) ? xf[r].y
                             : (kk == 2) ? xf[r].z : xf[r].w;
                    acc[r][0] += xv * w0[kk].x;
                    acc[r][1] += xv * w0[kk].y;
                    acc[r][2] += xv * w0[kk].z;
                    acc[r][3] += xv * w0[kk].w;
                    acc[r][4] += xv * w1[kk].x;
                    acc[r][5] += xv * w1[kk].y;
                    acc[r][6] += xv * w1[kk].z;
                    acc[r][7] += xv * w1[kk].w;
                }
            }
        }
        __syncthreads();
    }

    float4 b0 = *(const float4*)&bias[cbase];
    float4 b1 = *(const float4*)&bias[cbase + 4];
#pragma unroll
    for (int r = 0; r < 8; r++) {
        int row = row0 + rbase + r;
        if (row < nrows) {
            float4 o0, o1;
            o0.x = acc[r][0] + b0.x; o0.y = acc[r][1] + b0.y;
            o0.z = acc[r][2] + b0.z; o0.w = acc[r][3] + b0.w;
            o1.x = acc[r][4] + b1.x; o1.y = acc[r][5] + b1.y;
            o1.z = acc[r][6] + b1.z; o1.w = acc[r][7] + b1.w;
            *(float4*)&Y[(long)row * D + cbase]     = o0;
            *(float4*)&Y[(long)row * D + cbase + 4] = o1;
        }
    }
}

// ---------------------------------------------------------------------------
extern "C" void kernel_launch(void* const* d_in, const int* in_sizes, int n_in,
                              void* d_out, int out_size) {
    const float* h  = (const float*)d_in[0];
    const int*   ei = (const int*)d_in[1];
    const float* Wt[4] = { (const float*)d_in[2], (const float*)d_in[4],
                           (const float*)d_in[6], (const float*)d_in[8] };
    const float* bt[4] = { (const float*)d_in[3], (const float*)d_in[5],
                           (const float*)d_in[7], (const float*)d_in[9] };
    float* out = (float*)d_out;

    // build CSR (dst -> list of src) — 3 kernels so the 4th launch (profiled
    // slot) is the aggregate.
    count_deg_kernel<<<(N_EDGES + 255) / 256, 256>>>(ei);
    scan_deg_kernel<<<1, 1024>>>();
    fill_csr_kernel<<<(N_EDGES + 255) / 256, 256>>>(ei);

    const int agg_blocks  = N_NODES / 8;              // 2500
    const int gemm_blocks = (N_NODES + 127) / 128;    // 157

    aggregate_kernel<<<agg_blocks, 256>>>(h);
    gemm_kernel<<<gemm_blocks, 256>>>(Wt[0], bt[0], g_h, N_NODES);

    aggregate_kernel<<<agg_blocks, 256>>>(g_h);
    gemm_kernel<<<gemm_blocks, 256>>>(Wt[1], bt[1], g_h, N_NODES);

    aggregate_kernel<<<agg_blocks, 256>>>(g_h);
    gemm_kernel<<<gemm_blocks, 256>>>(Wt[2], bt[2], g_h, N_NODES);

    aggregate_kernel<<<agg_blocks, 256>>>(g_h);
    gemm_kernel<<<gemm_blocks, 256>>>(Wt[3], bt[3], out, N_NODES);
}